// round 15
// baseline (speedup 1.0000x reference)
#include <cuda_runtime.h>
#include <cuda.h>
#include <math.h>
#include <stdint.h>

#define SEQL 4096
#define BATCH 2
#define DMODEL 256
#define DINNER 512
#define NSTATE 16
#define DTRANK 16
#define M_TOT (BATCH*SEQL)    // 8192
#define NCHAIN (BATCH*DINNER) // 1024
#define NCHUNK 64
#define CLEN   (SEQL/NCHUNK)  // 64

// -------- scratch (device globals; no dynamic allocation) --------
__device__ float g_xz [(size_t)M_TOT * 1024];     // in-proj output (x_in | z)
__device__ float g_ut [(size_t)NCHAIN * SEQL];    // u transposed [chain][l]
__device__ float g_dtt[(size_t)NCHAIN * SEQL];    // softplus dt  [chain][l]
__device__ float g_dbl[(size_t)M_TOT * 48];       // [unused(16) | B(16) | C(16)]
__device__ float g_y  [(size_t)M_TOT * DINNER];   // scan output (post gating)
__device__ float g_P  [(size_t)NCHUNK * NCHAIN * NSTATE];
__device__ float g_hf [(size_t)NCHUNK * NCHAIN * NSTATE];
__device__ float g_hin[(size_t)NCHUNK * NCHAIN * NSTATE];

#define LOG2E 1.4426950408889634f

__device__ __forceinline__ float ex2f(float x) {
    float r; asm("ex2.approx.f32 %0, %1;" : "=f"(r) : "f"(x)); return r;
}
__device__ __forceinline__ float to_tf32(float x) {
    float r; asm("cvt.rna.tf32.f32 %0, %1;" : "=f"(r) : "f"(x)); return r;
}

// mma.sync m16n8k8 tf32 (base ISA, sm_80+)
__device__ __forceinline__ void mma_tf32(float* c, const uint32_t* a, const uint32_t* b) {
    asm volatile(
        "mma.sync.aligned.m16n8k8.row.col.f32.tf32.tf32.f32 "
        "{%0,%1,%2,%3}, {%4,%5,%6,%7}, {%8,%9}, {%0,%1,%2,%3};"
        : "+f"(c[0]), "+f"(c[1]), "+f"(c[2]), "+f"(c[3])
        : "r"(a[0]), "r"(a[1]), "r"(a[2]), "r"(a[3]), "r"(b[0]), "r"(b[1]));
}

// ============================================================
// K1: tf32 mma GEMM: xz[m][j] = sum_c x[b][c][l] * Win[j][c]
//     block 128x128, BK=32, 256 thr, As stride 136 (R14 exact)
// ============================================================
__global__ __launch_bounds__(256) void mma_gemm_in(const float* __restrict__ x,
                                                   const float* __restrict__ Win) {
    __shared__ float As[32][136];   // [k][m]
    __shared__ float Bs[128][36];   // [n][k]
    const int tid = threadIdx.x, lane = tid & 31, wid = tid >> 5;
    const int m0 = blockIdx.x * 128, n0 = blockIdx.y * 128;
    const int b = m0 / SEQL, l0 = m0 % SEQL;
    const float* xb = x + (size_t)b * DMODEL * SEQL;
    const int wm = (wid & 1) * 64;
    const int wn = (wid >> 1) * 32;
    const int row = lane >> 2, kc = lane & 3;

    float acc[4][4][4];
#pragma unroll
    for (int i = 0; i < 4; i++)
#pragma unroll
        for (int j = 0; j < 4; j++)
#pragma unroll
            for (int q = 0; q < 4; q++) acc[i][j][q] = 0.f;

    for (int kt = 0; kt < 8; kt++) {
        const int k0 = kt * 32;
#pragma unroll
        for (int r = 0; r < 4; r++) {
            const int idx = tid + r * 256;
            const int kk = idx >> 5, mm4 = (idx & 31) * 4;
            float4 v = *(const float4*)&xb[(size_t)(k0 + kk) * SEQL + l0 + mm4];
            v.x = to_tf32(v.x); v.y = to_tf32(v.y); v.z = to_tf32(v.z); v.w = to_tf32(v.w);
            *(float4*)&As[kk][mm4] = v;
        }
#pragma unroll
        for (int r = 0; r < 4; r++) {
            const int idx = tid + r * 256;
            const int jj = idx >> 3, kk4 = (idx & 7) * 4;
            float4 v = *(const float4*)&Win[(size_t)(n0 + jj) * DMODEL + k0 + kk4];
            v.x = to_tf32(v.x); v.y = to_tf32(v.y); v.z = to_tf32(v.z); v.w = to_tf32(v.w);
            *(float4*)&Bs[jj][kk4] = v;
        }
        __syncthreads();
#pragma unroll
        for (int s = 0; s < 4; s++) {
            const int ks = s * 8 + kc;
            uint32_t a[4][4], bf[4][2];
#pragma unroll
            for (int i = 0; i < 4; i++) {
                const int m1 = wm + i * 16 + row;
                a[i][0] = __float_as_uint(As[ks][m1]);
                a[i][1] = __float_as_uint(As[ks][m1 + 8]);
                a[i][2] = __float_as_uint(As[ks + 4][m1]);
                a[i][3] = __float_as_uint(As[ks + 4][m1 + 8]);
            }
#pragma unroll
            for (int j = 0; j < 4; j++) {
                const int n1 = wn + j * 8 + row;
                bf[j][0] = __float_as_uint(Bs[n1][ks]);
                bf[j][1] = __float_as_uint(Bs[n1][ks + 4]);
            }
#pragma unroll
            for (int i = 0; i < 4; i++)
#pragma unroll
                for (int j = 0; j < 4; j++) mma_tf32(acc[i][j], a[i], bf[j]);
        }
        __syncthreads();
    }
#pragma unroll
    for (int i = 0; i < 4; i++) {
        const int mrow = m0 + wm + i * 16 + row;
#pragma unroll
        for (int j = 0; j < 4; j++) {
            const int col = n0 + wn + j * 8 + kc * 2;
            *(float2*)&g_xz[(size_t)mrow * 1024 + col] = make_float2(acc[i][j][0], acc[i][j][1]);
            *(float2*)&g_xz[(size_t)(mrow + 8) * 1024 + col] = make_float2(acc[i][j][2], acc[i][j][3]);
        }
    }
}

// ============================================================
// K6: tf32 mma GEMM: out[b][c][l] = sum_d y[m][d]*Wout[c][d]
//     block 128x64, BK=32, 256 thr (R14 exact)
// ============================================================
__global__ __launch_bounds__(256) void mma_gemm_out(const float* __restrict__ Wout,
                                                    float* __restrict__ out) {
    __shared__ float As[128][36];   // [m][k]
    __shared__ float Bs[64][36];    // [n][k]
    const int tid = threadIdx.x, lane = tid & 31, wid = tid >> 5;
    const int m0 = blockIdx.x * 128, n0 = blockIdx.y * 64;
    const int wm = (wid & 1) * 64;
    const int wn = (wid >> 1) * 16;
    const int row = lane >> 2, kc = lane & 3;

    float acc[4][2][4];
#pragma unroll
    for (int i = 0; i < 4; i++)
#pragma unroll
        for (int j = 0; j < 2; j++)
#pragma unroll
            for (int q = 0; q < 4; q++) acc[i][j][q] = 0.f;

    for (int kt = 0; kt < 16; kt++) {
        const int k0 = kt * 32;
#pragma unroll
        for (int r = 0; r < 4; r++) {
            const int idx = tid + r * 256;
            const int mm = idx >> 3, kk4 = (idx & 7) * 4;
            float4 v = *(const float4*)&g_y[(size_t)(m0 + mm) * DINNER + k0 + kk4];
            v.x = to_tf32(v.x); v.y = to_tf32(v.y); v.z = to_tf32(v.z); v.w = to_tf32(v.w);
            *(float4*)&As[mm][kk4] = v;
        }
#pragma unroll
        for (int r = 0; r < 2; r++) {
            const int idx = tid + r * 256;
            const int nn = idx >> 3, kk4 = (idx & 7) * 4;
            float4 v = *(const float4*)&Wout[(size_t)(n0 + nn) * DINNER + k0 + kk4];
            v.x = to_tf32(v.x); v.y = to_tf32(v.y); v.z = to_tf32(v.z); v.w = to_tf32(v.w);
            *(float4*)&Bs[nn][kk4] = v;
        }
        __syncthreads();
#pragma unroll
        for (int s = 0; s < 4; s++) {
            const int ks = s * 8 + kc;
            uint32_t a[4][4], bf[2][2];
#pragma unroll
            for (int i = 0; i < 4; i++) {
                const int m1 = wm + i * 16 + row;
                a[i][0] = __float_as_uint(As[m1][ks]);
                a[i][1] = __float_as_uint(As[m1 + 8][ks]);
                a[i][2] = __float_as_uint(As[m1][ks + 4]);
                a[i][3] = __float_as_uint(As[m1 + 8][ks + 4]);
            }
#pragma unroll
            for (int j = 0; j < 2; j++) {
                const int n1 = wn + j * 8 + row;
                bf[j][0] = __float_as_uint(Bs[n1][ks]);
                bf[j][1] = __float_as_uint(Bs[n1][ks + 4]);
            }
#pragma unroll
            for (int i = 0; i < 4; i++)
#pragma unroll
                for (int j = 0; j < 2; j++) mma_tf32(acc[i][j], a[i], bf[j]);
        }
        __syncthreads();
    }
    const int b  = m0 / SEQL;
    const int l0 = m0 % SEQL;
#pragma unroll
    for (int i = 0; i < 4; i++) {
        const int l = l0 + wm + i * 16 + row;
#pragma unroll
        for (int j = 0; j < 2; j++) {
            const int col = n0 + wn + j * 8 + kc * 2;
            out[((size_t)b * DMODEL + col)     * SEQL + l]     = acc[i][j][0];
            out[((size_t)b * DMODEL + col + 1) * SEQL + l]     = acc[i][j][1];
            out[((size_t)b * DMODEL + col)     * SEQL + l + 8] = acc[i][j][2];
            out[((size_t)b * DMODEL + col + 1) * SEQL + l + 8] = acc[i][j][3];
        }
    }
}

// ============================================================
// K2: FUSED conv + bias + silu + transpose -> g_ut only (R14 exact)
// ============================================================
__global__ __launch_bounds__(256) void conv_silu_tr(const float* __restrict__ cw,
                                                    const float* __restrict__ cb) {
    __shared__ float s [67][68];
    __shared__ float su[64][68];
    const int b  = blockIdx.z;
    const int l0 = blockIdx.x * 64;
    const int d0 = blockIdx.y * 64;
    const int tid = threadIdx.x;

    for (int i = tid; i < 67 * 16; i += 256) {
        const int rr = i >> 4, c4 = (i & 15) * 4;
        const int l = l0 + rr - 3;
        float4 v = (l >= 0)
            ? *(const float4*)&g_xz[((size_t)b * SEQL + l) * 1024 + d0 + c4]
            : make_float4(0.f, 0.f, 0.f, 0.f);
        *(float4*)&s[rr][c4] = v;
    }
    __syncthreads();

    {
        const int dc = tid & 63;
        const int lb = (tid >> 6) * 16;
        const int d  = d0 + dc;
        const float4 w = *(const float4*)&cw[d * 4];
        const float bias = cb[d];
#pragma unroll
        for (int ll = 0; ll < 16; ll++) {
            const int lr = lb + ll;
            float a = bias + s[lr][dc] * w.x + s[lr + 1][dc] * w.y
                           + s[lr + 2][dc] * w.z + s[lr + 3][dc] * w.w;
            const float sg = 1.f / (1.f + __expf(-a));
            su[lr][dc] = a * sg;
        }
    }
    __syncthreads();

    for (int i = tid; i < 64 * 16; i += 256) {
        const int dr = i >> 4, c4 = (i & 15) * 4;
        float4 v = make_float4(su[c4 + 0][dr], su[c4 + 1][dr],
                               su[c4 + 2][dr], su[c4 + 3][dr]);
        *(float4*)&g_ut[((size_t)b * DINNER + d0 + dr) * SEQL + l0 + c4] = v;
    }
}

// ============================================================
// K3: FUSED x_dbl GEMM + dt projection + softplus.
//     Phase 1 (R14 xdbl): acc = u @ Wx^T for 64 rows.
//       cols 0..15 (dt_raw) -> smem rs; cols 16..47 (B|C) -> g_dbl.
//     Phase 2: dt[m][d] = softplus(rs[m].Wdt[d] + b_dt[d]) -> g_dtt,
//       2 d/thread x 4 m/iter = 8 independent FMA chains.
// ============================================================
__global__ __launch_bounds__(256) void gemm_xdbl_dt(const float* __restrict__ Wx,
                                                    const float* __restrict__ Wdt,
                                                    const float* __restrict__ bdt) {
    __shared__ float Us[16][68];
    __shared__ float Ws[16][48];
    __shared__ float rs[64][16];   // dt_raw tile (broadcast reads in phase 2)
    const int m0 = blockIdx.x * 64;
    const int b  = m0 / SEQL;
    const int l0 = m0 % SEQL;
    const int tid = threadIdx.x;
    const int tx = tid & 15, ty = tid >> 4;
    const int ukk = tid >> 4;
    const int ur4 = (tid & 15) * 4;
    const int wj   = (tid < 192) ? (tid >> 2) : 0;
    const int wkk4 = (tid & 3) * 4;
    const bool hasw = tid < 192;

    float acc[4][3];
#pragma unroll
    for (int i = 0; i < 4; i++)
#pragma unroll
        for (int j = 0; j < 3; j++) acc[i][j] = 0.f;

    float4 pu = *(const float4*)&g_ut[((size_t)b * DINNER + ukk) * SEQL + l0 + ur4];
    float4 pw = hasw ? *(const float4*)&Wx[(size_t)wj * DINNER + wkk4] : make_float4(0,0,0,0);

    for (int kt = 0; kt < 32; kt++) {
        *(float4*)&Us[ukk][ur4] = pu;
        if (hasw) {
            Ws[wkk4 + 0][wj] = pw.x; Ws[wkk4 + 1][wj] = pw.y;
            Ws[wkk4 + 2][wj] = pw.z; Ws[wkk4 + 3][wj] = pw.w;
        }
        __syncthreads();
        if (kt < 31) {
            const int k0 = (kt + 1) * 16;
            pu = *(const float4*)&g_ut[((size_t)b * DINNER + k0 + ukk) * SEQL + l0 + ur4];
            if (hasw) pw = *(const float4*)&Wx[(size_t)wj * DINNER + k0 + wkk4];
        }
#pragma unroll
        for (int kk = 0; kk < 16; kk++) {
            float ra[4], rb[3];
#pragma unroll
            for (int i = 0; i < 4; i++) ra[i] = Us[kk][ty * 4 + i];
#pragma unroll
            for (int j = 0; j < 3; j++) rb[j] = Ws[kk][tx * 3 + j];
#pragma unroll
            for (int i = 0; i < 4; i++)
#pragma unroll
                for (int j = 0; j < 3; j++) acc[i][j] += ra[i] * rb[j];
        }
        __syncthreads();
    }
    // epilogue: dt_raw cols -> smem; B|C cols -> g_dbl
#pragma unroll
    for (int i = 0; i < 4; i++) {
        const int mm = ty * 4 + i;
        const size_t m = (size_t)(m0 + mm);
#pragma unroll
        for (int j = 0; j < 3; j++) {
            const int col = tx * 3 + j;
            if (col < 16) rs[mm][col] = acc[i][j];
            else          g_dbl[m * 48 + col] = acc[i][j];
        }
    }
    __syncthreads();

    // ---- Phase 2: dt projection + softplus for this m-tile ----
    const int d0 = tid;           // d values: tid and tid+256
    const int d1 = tid + 256;
    float w0[16], w1[16];
#pragma unroll
    for (int q = 0; q < 4; q++) {
        float4 v0 = *(const float4*)&Wdt[(size_t)d0 * 16 + q * 4];
        float4 v1 = *(const float4*)&Wdt[(size_t)d1 * 16 + q * 4];
        w0[q*4+0]=v0.x; w0[q*4+1]=v0.y; w0[q*4+2]=v0.z; w0[q*4+3]=v0.w;
        w1[q*4+0]=v1.x; w1[q*4+1]=v1.y; w1[q*4+2]=v1.z; w1[q*4+3]=v1.w;
    }
    const float b0 = bdt[d0], b1 = bdt[d1];
    float* dst0 = &g_dtt[((size_t)b * DINNER + d0) * SEQL + l0];
    float* dst1 = &g_dtt[((size_t)b * DINNER + d1) * SEQL + l0];

    for (int mm = 0; mm < 64; mm += 4) {
        float a0 = b0, a1 = b0, a2 = b0, a3 = b0;
        float c0 = b1, c1 = b1, c2 = b1, c3 = b1;
#pragma unroll
        for (int k = 0; k < 16; k++) {
            const float r0 = rs[mm][k], r1 = rs[mm+1][k];
            const float r2 = rs[mm+2][k], r3 = rs[mm+3][k];
            a0 += r0 * w0[k]; a1 += r1 * w0[k];
            a2 += r2 * w0[k]; a3 += r3 * w0[k];
            c0 += r0 * w1[k]; c1 += r1 * w1[k];
            c2 += r2 * w1[k]; c3 += r3 * w1[k];
        }
        const float s0 = fmaxf(a0,0.f) + __logf(1.f + __expf(-fabsf(a0)));
        const float s1 = fmaxf(a1,0.f) + __logf(1.f + __expf(-fabsf(a1)));
        const float s2 = fmaxf(a2,0.f) + __logf(1.f + __expf(-fabsf(a2)));
        const float s3 = fmaxf(a3,0.f) + __logf(1.f + __expf(-fabsf(a3)));
        const float t0 = fmaxf(c0,0.f) + __logf(1.f + __expf(-fabsf(c0)));
        const float t1 = fmaxf(c1,0.f) + __logf(1.f + __expf(-fabsf(c1)));
        const float t2 = fmaxf(c2,0.f) + __logf(1.f + __expf(-fabsf(c2)));
        const float t3 = fmaxf(c3,0.f) + __logf(1.f + __expf(-fabsf(c3)));
        *(float4*)&dst0[mm] = make_float4(s0, s1, s2, s3);
        *(float4*)&dst1[mm] = make_float4(t0, t1, t2, t3);
    }
}

// ============================================================
// K5a: chunked scan pass 1  (R14 exact — now launch slot 4)
// ============================================================
__global__ __launch_bounds__(128) void scan_p1(const float* __restrict__ A_log) {
    const int hw    = (blockIdx.x * blockDim.x + threadIdx.x) >> 4;
    const int g     = threadIdx.x & 15;
    const int chain = hw & (NCHAIN - 1);
    const int chunk = hw >> 10;
    const int b = chain >> 9;
    const int d = chain & (DINNER - 1);
    const float A2 = -__expf(A_log[d * 16 + g]) * LOG2E;
    float h = 0.f, sdt = 0.f;
    const float* dtp = &g_dtt[(size_t)chain * SEQL + chunk * CLEN];
    const float* up  = &g_ut [(size_t)chain * SEQL + chunk * CLEN];
    const size_t mbase = (size_t)b * SEQL + chunk * CLEN;
    for (int i0 = 0; i0 < CLEN; i0 += 4) {
        const float4 dt4 = *(const float4*)&dtp[i0];
        const float4 u4  = *(const float4*)&up[i0];
        const float dts[4] = {dt4.x, dt4.y, dt4.z, dt4.w};
        const float us [4] = {u4.x, u4.y, u4.z, u4.w};
#pragma unroll
        for (int k = 0; k < 4; k++) {
            const float dt = dts[k];
            const float Bv = g_dbl[(mbase + i0 + k) * 48 + 16 + g];
            const float a  = ex2f(dt * A2);
            h = a * h + (dt * us[k]) * Bv;
            sdt += dt;
        }
    }
    const size_t o = ((size_t)chunk * NCHAIN + chain) * NSTATE + g;
    g_P [o] = ex2f(sdt * A2);
    g_hf[o] = h;
}

// ============================================================
// K5b: combine across chunks  (R14 exact)
// ============================================================
__global__ void scan_combine() {
    const int t = blockIdx.x * blockDim.x + threadIdx.x;
    float h = 0.f;
#pragma unroll 4
    for (int c = 0; c < NCHUNK; c++) {
        const size_t o = (size_t)c * (NCHAIN * NSTATE) + t;
        g_hin[o] = h;
        h = g_P[o] * h + g_hf[o];
    }
}

// ============================================================
// K5c: pass 3  (R14 exact)
// ============================================================
__global__ __launch_bounds__(128) void scan_p3(const float* __restrict__ A_log,
                                               const float* __restrict__ Dp) {
    const int hw    = (blockIdx.x * blockDim.x + threadIdx.x) >> 4;
    const int g     = threadIdx.x & 15;
    const int chain = hw & (NCHAIN - 1);
    const int chunk = hw >> 10;
    const int b = chain >> 9;
    const int d = chain & (DINNER - 1);
    const float A2 = -__expf(A_log[d * 16 + g]) * LOG2E;
    const float dp = Dp[d];
    float h = g_hin[((size_t)chunk * NCHAIN + chain) * NSTATE + g];
    const float* dtp = &g_dtt[(size_t)chain * SEQL + chunk * CLEN];
    const float* up  = &g_ut [(size_t)chain * SEQL + chunk * CLEN];
    const size_t mbase = (size_t)b * SEQL + chunk * CLEN;
    for (int i0 = 0; i0 < CLEN; i0 += 4) {
        const float4 dt4 = *(const float4*)&dtp[i0];
        const float4 u4  = *(const float4*)&up[i0];
        const float dts[4] = {dt4.x, dt4.y, dt4.z, dt4.w};
        const float us [4] = {u4.x, u4.y, u4.z, u4.w};
#pragma unroll
        for (int k = 0; k < 4; k++) {
            const size_t m = mbase + i0 + k;
            const float dt = dts[k];
            const float u  = us[k];
            const float Bv = g_dbl[m * 48 + 16 + g];
            const float Cv = g_dbl[m * 48 + 32 + g];
            const float a  = ex2f(dt * A2);
            h = a * h + (dt * u) * Bv;
            float p = h * Cv;
            p += __shfl_xor_sync(0xffffffffu, p, 8, 16);
            p += __shfl_xor_sync(0xffffffffu, p, 4, 16);
            p += __shfl_xor_sync(0xffffffffu, p, 2, 16);
            p += __shfl_xor_sync(0xffffffffu, p, 1, 16);
            if (g == 0) {
                const float z  = g_xz[m * 1024 + 512 + d];
                const float sg = 1.f / (1.f + __expf(-z));
                g_y[m * DINNER + d] = (p + u * dp) * (z * sg);
            }
        }
    }
}

// ============================================================
extern "C" void kernel_launch(void* const* d_in, const int* in_sizes, int n_in,
                              void* d_out, int out_size) {
    const float* x    = (const float*)d_in[0];
    const float* Win  = (const float*)d_in[1];
    const float* cw   = (const float*)d_in[2];
    const float* cb   = (const float*)d_in[3];
    const float* Wx   = (const float*)d_in[4];
    const float* Wdt  = (const float*)d_in[5];
    const float* bdt  = (const float*)d_in[6];
    const float* Alog = (const float*)d_in[7];
    const float* Dp   = (const float*)d_in[8];
    const float* Wout = (const float*)d_in[9];
    float* out = (float*)d_out;

    dim3 g1(M_TOT / 128, 1024 / 128);           // 64 x 8
    mma_gemm_in<<<g1, 256>>>(x, Win);

    dim3 gc(SEQL / 64, DINNER / 64, BATCH);     // fused conv+silu+transpose
    conv_silu_tr<<<gc, 256>>>(cw, cb);

    gemm_xdbl_dt<<<M_TOT / 64, 256>>>(Wx, Wdt, bdt);  // fused xdbl + dt

    const int blocks = NCHUNK * NCHAIN * 16 / 128; // 8192
    scan_p1<<<blocks, 128>>>(Alog);                 // <- profile slot 4
    scan_combine<<<64, 256>>>();
    scan_p3<<<blocks, 128>>>(Alog, Dp);

    dim3 g2(M_TOT / 128, DMODEL / 64);          // 64 x 4
    mma_gemm_out<<<g2, 256>>>(Wout, out);
}

// round 16
// speedup vs baseline: 1.4619x; 1.4619x over previous
#include <cuda_runtime.h>
#include <cuda.h>
#include <math.h>
#include <stdint.h>

#define SEQL 4096
#define BATCH 2
#define DMODEL 256
#define DINNER 512
#define NSTATE 16
#define DTRANK 16
#define M_TOT (BATCH*SEQL)    // 8192
#define NCHAIN (BATCH*DINNER) // 1024
#define NCHUNK 64
#define CLEN   (SEQL/NCHUNK)  // 64

// -------- scratch (device globals; no dynamic allocation) --------
__device__ float g_xz [(size_t)M_TOT * 1024];     // in-proj output (x_in | z)
__device__ float g_ut [(size_t)NCHAIN * SEQL];    // u transposed [chain][l]
__device__ float g_dtt[(size_t)NCHAIN * SEQL];    // softplus dt  [chain][l]
__device__ float g_dbl[(size_t)M_TOT * 48];       // [unused(16) | B(16) | C(16)]
__device__ float g_y  [(size_t)M_TOT * DINNER];   // scan output (post gating)
__device__ float g_P  [(size_t)NCHUNK * NCHAIN * NSTATE];
__device__ float g_hf [(size_t)NCHUNK * NCHAIN * NSTATE];
__device__ float g_hin[(size_t)NCHUNK * NCHAIN * NSTATE];

#define LOG2E 1.4426950408889634f

__device__ __forceinline__ float ex2f(float x) {
    float r; asm("ex2.approx.f32 %0, %1;" : "=f"(r) : "f"(x)); return r;
}
__device__ __forceinline__ float to_tf32(float x) {
    float r; asm("cvt.rna.tf32.f32 %0, %1;" : "=f"(r) : "f"(x)); return r;
}

// mma.sync m16n8k8 tf32 (base ISA, sm_80+)
__device__ __forceinline__ void mma_tf32(float* c, const uint32_t* a, const uint32_t* b) {
    asm volatile(
        "mma.sync.aligned.m16n8k8.row.col.f32.tf32.tf32.f32 "
        "{%0,%1,%2,%3}, {%4,%5,%6,%7}, {%8,%9}, {%0,%1,%2,%3};"
        : "+f"(c[0]), "+f"(c[1]), "+f"(c[2]), "+f"(c[3])
        : "r"(a[0]), "r"(a[1]), "r"(a[2]), "r"(a[3]), "r"(b[0]), "r"(b[1]));
}

// ============================================================
// K1: tf32 mma GEMM: xz[m][j] = sum_c x[b][c][l] * Win[j][c]  (R15 exact)
// ============================================================
__global__ __launch_bounds__(256) void mma_gemm_in(const float* __restrict__ x,
                                                   const float* __restrict__ Win) {
    __shared__ float As[32][136];   // [k][m]
    __shared__ float Bs[128][36];   // [n][k]
    const int tid = threadIdx.x, lane = tid & 31, wid = tid >> 5;
    const int m0 = blockIdx.x * 128, n0 = blockIdx.y * 128;
    const int b = m0 / SEQL, l0 = m0 % SEQL;
    const float* xb = x + (size_t)b * DMODEL * SEQL;
    const int wm = (wid & 1) * 64;
    const int wn = (wid >> 1) * 32;
    const int row = lane >> 2, kc = lane & 3;

    float acc[4][4][4];
#pragma unroll
    for (int i = 0; i < 4; i++)
#pragma unroll
        for (int j = 0; j < 4; j++)
#pragma unroll
            for (int q = 0; q < 4; q++) acc[i][j][q] = 0.f;

    for (int kt = 0; kt < 8; kt++) {
        const int k0 = kt * 32;
#pragma unroll
        for (int r = 0; r < 4; r++) {
            const int idx = tid + r * 256;
            const int kk = idx >> 5, mm4 = (idx & 31) * 4;
            float4 v = *(const float4*)&xb[(size_t)(k0 + kk) * SEQL + l0 + mm4];
            v.x = to_tf32(v.x); v.y = to_tf32(v.y); v.z = to_tf32(v.z); v.w = to_tf32(v.w);
            *(float4*)&As[kk][mm4] = v;
        }
#pragma unroll
        for (int r = 0; r < 4; r++) {
            const int idx = tid + r * 256;
            const int jj = idx >> 3, kk4 = (idx & 7) * 4;
            float4 v = *(const float4*)&Win[(size_t)(n0 + jj) * DMODEL + k0 + kk4];
            v.x = to_tf32(v.x); v.y = to_tf32(v.y); v.z = to_tf32(v.z); v.w = to_tf32(v.w);
            *(float4*)&Bs[jj][kk4] = v;
        }
        __syncthreads();
#pragma unroll
        for (int s = 0; s < 4; s++) {
            const int ks = s * 8 + kc;
            uint32_t a[4][4], bf[4][2];
#pragma unroll
            for (int i = 0; i < 4; i++) {
                const int m1 = wm + i * 16 + row;
                a[i][0] = __float_as_uint(As[ks][m1]);
                a[i][1] = __float_as_uint(As[ks][m1 + 8]);
                a[i][2] = __float_as_uint(As[ks + 4][m1]);
                a[i][3] = __float_as_uint(As[ks + 4][m1 + 8]);
            }
#pragma unroll
            for (int j = 0; j < 4; j++) {
                const int n1 = wn + j * 8 + row;
                bf[j][0] = __float_as_uint(Bs[n1][ks]);
                bf[j][1] = __float_as_uint(Bs[n1][ks + 4]);
            }
#pragma unroll
            for (int i = 0; i < 4; i++)
#pragma unroll
                for (int j = 0; j < 4; j++) mma_tf32(acc[i][j], a[i], bf[j]);
        }
        __syncthreads();
    }
#pragma unroll
    for (int i = 0; i < 4; i++) {
        const int mrow = m0 + wm + i * 16 + row;
#pragma unroll
        for (int j = 0; j < 4; j++) {
            const int col = n0 + wn + j * 8 + kc * 2;
            *(float2*)&g_xz[(size_t)mrow * 1024 + col] = make_float2(acc[i][j][0], acc[i][j][1]);
            *(float2*)&g_xz[(size_t)(mrow + 8) * 1024 + col] = make_float2(acc[i][j][2], acc[i][j][3]);
        }
    }
}

// ============================================================
// K6: tf32 mma GEMM: out[b][c][l] = sum_d y[m][d]*Wout[c][d]  (R15 exact)
// ============================================================
__global__ __launch_bounds__(256) void mma_gemm_out(const float* __restrict__ Wout,
                                                    float* __restrict__ out) {
    __shared__ float As[128][36];   // [m][k]
    __shared__ float Bs[64][36];    // [n][k]
    const int tid = threadIdx.x, lane = tid & 31, wid = tid >> 5;
    const int m0 = blockIdx.x * 128, n0 = blockIdx.y * 64;
    const int wm = (wid & 1) * 64;
    const int wn = (wid >> 1) * 16;
    const int row = lane >> 2, kc = lane & 3;

    float acc[4][2][4];
#pragma unroll
    for (int i = 0; i < 4; i++)
#pragma unroll
        for (int j = 0; j < 2; j++)
#pragma unroll
            for (int q = 0; q < 4; q++) acc[i][j][q] = 0.f;

    for (int kt = 0; kt < 16; kt++) {
        const int k0 = kt * 32;
#pragma unroll
        for (int r = 0; r < 4; r++) {
            const int idx = tid + r * 256;
            const int mm = idx >> 3, kk4 = (idx & 7) * 4;
            float4 v = *(const float4*)&g_y[(size_t)(m0 + mm) * DINNER + k0 + kk4];
            v.x = to_tf32(v.x); v.y = to_tf32(v.y); v.z = to_tf32(v.z); v.w = to_tf32(v.w);
            *(float4*)&As[mm][kk4] = v;
        }
#pragma unroll
        for (int r = 0; r < 2; r++) {
            const int idx = tid + r * 256;
            const int nn = idx >> 3, kk4 = (idx & 7) * 4;
            float4 v = *(const float4*)&Wout[(size_t)(n0 + nn) * DINNER + k0 + kk4];
            v.x = to_tf32(v.x); v.y = to_tf32(v.y); v.z = to_tf32(v.z); v.w = to_tf32(v.w);
            *(float4*)&Bs[nn][kk4] = v;
        }
        __syncthreads();
#pragma unroll
        for (int s = 0; s < 4; s++) {
            const int ks = s * 8 + kc;
            uint32_t a[4][4], bf[2][2];
#pragma unroll
            for (int i = 0; i < 4; i++) {
                const int m1 = wm + i * 16 + row;
                a[i][0] = __float_as_uint(As[m1][ks]);
                a[i][1] = __float_as_uint(As[m1 + 8][ks]);
                a[i][2] = __float_as_uint(As[m1][ks + 4]);
                a[i][3] = __float_as_uint(As[m1 + 8][ks + 4]);
            }
#pragma unroll
            for (int j = 0; j < 2; j++) {
                const int n1 = wn + j * 8 + row;
                bf[j][0] = __float_as_uint(Bs[n1][ks]);
                bf[j][1] = __float_as_uint(Bs[n1][ks + 4]);
            }
#pragma unroll
            for (int i = 0; i < 4; i++)
#pragma unroll
                for (int j = 0; j < 2; j++) mma_tf32(acc[i][j], a[i], bf[j]);
        }
        __syncthreads();
    }
    const int b  = m0 / SEQL;
    const int l0 = m0 % SEQL;
#pragma unroll
    for (int i = 0; i < 4; i++) {
        const int l = l0 + wm + i * 16 + row;
#pragma unroll
        for (int j = 0; j < 2; j++) {
            const int col = n0 + wn + j * 8 + kc * 2;
            out[((size_t)b * DMODEL + col)     * SEQL + l]     = acc[i][j][0];
            out[((size_t)b * DMODEL + col + 1) * SEQL + l]     = acc[i][j][1];
            out[((size_t)b * DMODEL + col)     * SEQL + l + 8] = acc[i][j][2];
            out[((size_t)b * DMODEL + col + 1) * SEQL + l + 8] = acc[i][j][3];
        }
    }
}

// ============================================================
// K2: FUSED conv + bias + silu + transpose -> g_ut only (R15 exact)
// ============================================================
__global__ __launch_bounds__(256) void conv_silu_tr(const float* __restrict__ cw,
                                                    const float* __restrict__ cb) {
    __shared__ float s [67][68];
    __shared__ float su[64][68];
    const int b  = blockIdx.z;
    const int l0 = blockIdx.x * 64;
    const int d0 = blockIdx.y * 64;
    const int tid = threadIdx.x;

    for (int i = tid; i < 67 * 16; i += 256) {
        const int rr = i >> 4, c4 = (i & 15) * 4;
        const int l = l0 + rr - 3;
        float4 v = (l >= 0)
            ? *(const float4*)&g_xz[((size_t)b * SEQL + l) * 1024 + d0 + c4]
            : make_float4(0.f, 0.f, 0.f, 0.f);
        *(float4*)&s[rr][c4] = v;
    }
    __syncthreads();

    {
        const int dc = tid & 63;
        const int lb = (tid >> 6) * 16;
        const int d  = d0 + dc;
        const float4 w = *(const float4*)&cw[d * 4];
        const float bias = cb[d];
#pragma unroll
        for (int ll = 0; ll < 16; ll++) {
            const int lr = lb + ll;
            float a = bias + s[lr][dc] * w.x + s[lr + 1][dc] * w.y
                           + s[lr + 2][dc] * w.z + s[lr + 3][dc] * w.w;
            const float sg = 1.f / (1.f + __expf(-a));
            su[lr][dc] = a * sg;
        }
    }
    __syncthreads();

    for (int i = tid; i < 64 * 16; i += 256) {
        const int dr = i >> 4, c4 = (i & 15) * 4;
        float4 v = make_float4(su[c4 + 0][dr], su[c4 + 1][dr],
                               su[c4 + 2][dr], su[c4 + 3][dr]);
        *(float4*)&g_ut[((size_t)b * DINNER + d0 + dr) * SEQL + l0 + c4] = v;
    }
}

// ============================================================
// K3: FUSED x_dbl GEMM + dt projection + softplus  (R15 exact)
// ============================================================
__global__ __launch_bounds__(256) void gemm_xdbl_dt(const float* __restrict__ Wx,
                                                    const float* __restrict__ Wdt,
                                                    const float* __restrict__ bdt) {
    __shared__ float Us[16][68];
    __shared__ float Ws[16][48];
    __shared__ float rs[64][16];
    const int m0 = blockIdx.x * 64;
    const int b  = m0 / SEQL;
    const int l0 = m0 % SEQL;
    const int tid = threadIdx.x;
    const int tx = tid & 15, ty = tid >> 4;
    const int ukk = tid >> 4;
    const int ur4 = (tid & 15) * 4;
    const int wj   = (tid < 192) ? (tid >> 2) : 0;
    const int wkk4 = (tid & 3) * 4;
    const bool hasw = tid < 192;

    float acc[4][3];
#pragma unroll
    for (int i = 0; i < 4; i++)
#pragma unroll
        for (int j = 0; j < 3; j++) acc[i][j] = 0.f;

    float4 pu = *(const float4*)&g_ut[((size_t)b * DINNER + ukk) * SEQL + l0 + ur4];
    float4 pw = hasw ? *(const float4*)&Wx[(size_t)wj * DINNER + wkk4] : make_float4(0,0,0,0);

    for (int kt = 0; kt < 32; kt++) {
        *(float4*)&Us[ukk][ur4] = pu;
        if (hasw) {
            Ws[wkk4 + 0][wj] = pw.x; Ws[wkk4 + 1][wj] = pw.y;
            Ws[wkk4 + 2][wj] = pw.z; Ws[wkk4 + 3][wj] = pw.w;
        }
        __syncthreads();
        if (kt < 31) {
            const int k0 = (kt + 1) * 16;
            pu = *(const float4*)&g_ut[((size_t)b * DINNER + k0 + ukk) * SEQL + l0 + ur4];
            if (hasw) pw = *(const float4*)&Wx[(size_t)wj * DINNER + k0 + wkk4];
        }
#pragma unroll
        for (int kk = 0; kk < 16; kk++) {
            float ra[4], rb[3];
#pragma unroll
            for (int i = 0; i < 4; i++) ra[i] = Us[kk][ty * 4 + i];
#pragma unroll
            for (int j = 0; j < 3; j++) rb[j] = Ws[kk][tx * 3 + j];
#pragma unroll
            for (int i = 0; i < 4; i++)
#pragma unroll
                for (int j = 0; j < 3; j++) acc[i][j] += ra[i] * rb[j];
        }
        __syncthreads();
    }
#pragma unroll
    for (int i = 0; i < 4; i++) {
        const int mm = ty * 4 + i;
        const size_t m = (size_t)(m0 + mm);
#pragma unroll
        for (int j = 0; j < 3; j++) {
            const int col = tx * 3 + j;
            if (col < 16) rs[mm][col] = acc[i][j];
            else          g_dbl[m * 48 + col] = acc[i][j];
        }
    }
    __syncthreads();

    const int d0 = tid;
    const int d1 = tid + 256;
    float w0[16], w1[16];
#pragma unroll
    for (int q = 0; q < 4; q++) {
        float4 v0 = *(const float4*)&Wdt[(size_t)d0 * 16 + q * 4];
        float4 v1 = *(const float4*)&Wdt[(size_t)d1 * 16 + q * 4];
        w0[q*4+0]=v0.x; w0[q*4+1]=v0.y; w0[q*4+2]=v0.z; w0[q*4+3]=v0.w;
        w1[q*4+0]=v1.x; w1[q*4+1]=v1.y; w1[q*4+2]=v1.z; w1[q*4+3]=v1.w;
    }
    const float b0 = bdt[d0], b1 = bdt[d1];
    float* dst0 = &g_dtt[((size_t)b * DINNER + d0) * SEQL + l0];
    float* dst1 = &g_dtt[((size_t)b * DINNER + d1) * SEQL + l0];

    for (int mm = 0; mm < 64; mm += 4) {
        float a0 = b0, a1 = b0, a2 = b0, a3 = b0;
        float c0 = b1, c1 = b1, c2 = b1, c3 = b1;
#pragma unroll
        for (int k = 0; k < 16; k++) {
            const float r0 = rs[mm][k], r1 = rs[mm+1][k];
            const float r2 = rs[mm+2][k], r3 = rs[mm+3][k];
            a0 += r0 * w0[k]; a1 += r1 * w0[k];
            a2 += r2 * w0[k]; a3 += r3 * w0[k];
            c0 += r0 * w1[k]; c1 += r1 * w1[k];
            c2 += r2 * w1[k]; c3 += r3 * w1[k];
        }
        const float s0 = fmaxf(a0,0.f) + __logf(1.f + __expf(-fabsf(a0)));
        const float s1 = fmaxf(a1,0.f) + __logf(1.f + __expf(-fabsf(a1)));
        const float s2 = fmaxf(a2,0.f) + __logf(1.f + __expf(-fabsf(a2)));
        const float s3 = fmaxf(a3,0.f) + __logf(1.f + __expf(-fabsf(a3)));
        const float t0 = fmaxf(c0,0.f) + __logf(1.f + __expf(-fabsf(c0)));
        const float t1 = fmaxf(c1,0.f) + __logf(1.f + __expf(-fabsf(c1)));
        const float t2 = fmaxf(c2,0.f) + __logf(1.f + __expf(-fabsf(c2)));
        const float t3 = fmaxf(c3,0.f) + __logf(1.f + __expf(-fabsf(c3)));
        *(float4*)&dst0[mm] = make_float4(s0, s1, s2, s3);
        *(float4*)&dst1[mm] = make_float4(t0, t1, t2, t3);
    }
}

// ============================================================
// K5a: scan pass 1 — 4 lanes/chain, 4 states/lane (float4 B loads,
//      in-register partial reduce). 8 chains per warp.
// ============================================================
__global__ __launch_bounds__(128) void scan_p1(const float* __restrict__ A_log) {
    const int gtid  = blockIdx.x * blockDim.x + threadIdx.x;
    const int wkr   = gtid >> 2;              // chain-chunk worker
    const int g4    = (threadIdx.x & 3) * 4;  // state base (0,4,8,12)
    const int chain = wkr & (NCHAIN - 1);
    const int chunk = wkr >> 10;
    const int b = chain >> 9;
    const int d = chain & (DINNER - 1);

    float4 Al = *(const float4*)&A_log[d * 16 + g4];
    float A2[4] = { -__expf(Al.x) * LOG2E, -__expf(Al.y) * LOG2E,
                    -__expf(Al.z) * LOG2E, -__expf(Al.w) * LOG2E };
    float h[4] = {0.f, 0.f, 0.f, 0.f};
    float sdt = 0.f;
    const float* dtp = &g_dtt[(size_t)chain * SEQL + chunk * CLEN];
    const float* up  = &g_ut [(size_t)chain * SEQL + chunk * CLEN];
    const size_t mbase = (size_t)b * SEQL + chunk * CLEN;

    for (int i0 = 0; i0 < CLEN; i0 += 4) {
        const float4 dt4 = *(const float4*)&dtp[i0];
        const float4 u4  = *(const float4*)&up[i0];
        const float dts[4] = {dt4.x, dt4.y, dt4.z, dt4.w};
        const float us [4] = {u4.x, u4.y, u4.z, u4.w};
#pragma unroll
        for (int k = 0; k < 4; k++) {
            const float dt = dts[k];
            const float du = dt * us[k];
            const float4 B4 = *(const float4*)&g_dbl[(mbase + i0 + k) * 48 + 16 + g4];
            h[0] = ex2f(dt * A2[0]) * h[0] + du * B4.x;
            h[1] = ex2f(dt * A2[1]) * h[1] + du * B4.y;
            h[2] = ex2f(dt * A2[2]) * h[2] + du * B4.z;
            h[3] = ex2f(dt * A2[3]) * h[3] + du * B4.w;
            sdt += dt;
        }
    }
    const size_t o4 = ((size_t)chunk * NCHAIN + chain) * NSTATE + g4;
    *(float4*)&g_P[o4]  = make_float4(ex2f(sdt * A2[0]), ex2f(sdt * A2[1]),
                                      ex2f(sdt * A2[2]), ex2f(sdt * A2[3]));
    *(float4*)&g_hf[o4] = make_float4(h[0], h[1], h[2], h[3]);
}

// ============================================================
// K5b: combine across chunks (unchanged)
// ============================================================
__global__ void scan_combine() {
    const int t = blockIdx.x * blockDim.x + threadIdx.x;
    float h = 0.f;
#pragma unroll 4
    for (int c = 0; c < NCHUNK; c++) {
        const size_t o = (size_t)c * (NCHAIN * NSTATE) + t;
        g_hin[o] = h;
        h = g_P[o] * h + g_hf[o];
    }
}

// ============================================================
// K5c: scan pass 3 — 4 lanes/chain layout; reduce = 3 FMA + 2 shfl
// ============================================================
__global__ __launch_bounds__(128) void scan_p3(const float* __restrict__ A_log,
                                               const float* __restrict__ Dp) {
    const int gtid  = blockIdx.x * blockDim.x + threadIdx.x;
    const int wkr   = gtid >> 2;
    const int g4    = (threadIdx.x & 3) * 4;
    const int chain = wkr & (NCHAIN - 1);
    const int chunk = wkr >> 10;
    const int b = chain >> 9;
    const int d = chain & (DINNER - 1);

    float4 Al = *(const float4*)&A_log[d * 16 + g4];
    float A2[4] = { -__expf(Al.x) * LOG2E, -__expf(Al.y) * LOG2E,
                    -__expf(Al.z) * LOG2E, -__expf(Al.w) * LOG2E };
    const float dp = Dp[d];
    float4 h4 = *(const float4*)&g_hin[((size_t)chunk * NCHAIN + chain) * NSTATE + g4];
    float h[4] = {h4.x, h4.y, h4.z, h4.w};
    const float* dtp = &g_dtt[(size_t)chain * SEQL + chunk * CLEN];
    const float* up  = &g_ut [(size_t)chain * SEQL + chunk * CLEN];
    const size_t mbase = (size_t)b * SEQL + chunk * CLEN;
    const bool lead = (threadIdx.x & 3) == 0;

    for (int i0 = 0; i0 < CLEN; i0 += 4) {
        const float4 dt4 = *(const float4*)&dtp[i0];
        const float4 u4  = *(const float4*)&up[i0];
        const float dts[4] = {dt4.x, dt4.y, dt4.z, dt4.w};
        const float us [4] = {u4.x, u4.y, u4.z, u4.w};
#pragma unroll
        for (int k = 0; k < 4; k++) {
            const size_t m = mbase + i0 + k;
            const float dt = dts[k];
            const float u  = us[k];
            const float du = dt * u;
            const float4 B4 = *(const float4*)&g_dbl[m * 48 + 16 + g4];
            const float4 C4 = *(const float4*)&g_dbl[m * 48 + 32 + g4];
            h[0] = ex2f(dt * A2[0]) * h[0] + du * B4.x;
            h[1] = ex2f(dt * A2[1]) * h[1] + du * B4.y;
            h[2] = ex2f(dt * A2[2]) * h[2] + du * B4.z;
            h[3] = ex2f(dt * A2[3]) * h[3] + du * B4.w;
            float p = h[0] * C4.x;
            p = fmaf(h[1], C4.y, p);
            p = fmaf(h[2], C4.z, p);
            p = fmaf(h[3], C4.w, p);
            p += __shfl_xor_sync(0xffffffffu, p, 1, 4);
            p += __shfl_xor_sync(0xffffffffu, p, 2, 4);
            if (lead) {
                const float z  = g_xz[m * 1024 + 512 + d];
                const float sg = 1.f / (1.f + __expf(-z));
                g_y[m * DINNER + d] = (p + u * dp) * (z * sg);
            }
        }
    }
}

// ============================================================
extern "C" void kernel_launch(void* const* d_in, const int* in_sizes, int n_in,
                              void* d_out, int out_size) {
    const float* x    = (const float*)d_in[0];
    const float* Win  = (const float*)d_in[1];
    const float* cw   = (const float*)d_in[2];
    const float* cb   = (const float*)d_in[3];
    const float* Wx   = (const float*)d_in[4];
    const float* Wdt  = (const float*)d_in[5];
    const float* bdt  = (const float*)d_in[6];
    const float* Alog = (const float*)d_in[7];
    const float* Dp   = (const float*)d_in[8];
    const float* Wout = (const float*)d_in[9];
    float* out = (float*)d_out;

    dim3 g1(M_TOT / 128, 1024 / 128);           // 64 x 8
    mma_gemm_in<<<g1, 256>>>(x, Win);

    dim3 gc(SEQL / 64, DINNER / 64, BATCH);     // fused conv+silu+transpose
    conv_silu_tr<<<gc, 256>>>(cw, cb);

    gemm_xdbl_dt<<<M_TOT / 64, 256>>>(Wx, Wdt, bdt);  // fused xdbl + dt

    const int scan_threads = NCHUNK * NCHAIN * 4;      // 262144
    scan_p1<<<scan_threads / 128, 128>>>(Alog);        // <- profile slot 4
    scan_combine<<<64, 256>>>();
    scan_p3<<<scan_threads / 128, 128>>>(Alog, Dp);

    dim3 g2(M_TOT / 128, DMODEL / 64);          // 64 x 4
    mma_gemm_out<<<g2, 256>>>(Wout, out);
}